// round 1
// baseline (speedup 1.0000x reference)
#include <cuda_runtime.h>
#include <cuda_fp16.h>
#include <mma.h>

using namespace nvcuda;

#define QDIM 4096   // q_dim (output rows)
#define NDIM 4096   // contraction dim of GEMM1 (rows of queries/keys)
#define MDIM 8192   // softmax dim / contraction of GEMM2
#define VDIM 4096   // v_dim (output cols)

// ---------------- scratch (static device globals; no runtime allocation) ----
__device__ __half g_Qt[(size_t)QDIM * NDIM];   // 32 MB : Qt[i][n] = Q[n][i]
__device__ __half g_Kc[(size_t)NDIM * MDIM];   // 64 MB : K[n][j]
__device__ __half g_Vt[(size_t)MDIM * VDIM];   // 64 MB : Vt[j][v] = V[v][j]
__device__ float  g_S [(size_t)QDIM * MDIM];   // 128 MB : logits (unscaled)
__device__ __half g_P [(size_t)QDIM * MDIM];   // 64 MB : exp(x - max) (UNNORMALIZED)
__device__ float  g_rsum[QDIM];                // row sums of exp

// ---------------- transpose + fp32->fp16 convert ----------------------------
// in:  rows x cols (fp32), out: cols x rows (fp16), out[c][r] = in[r][c]
__global__ void transpose_f2h(const float* __restrict__ in, __half* __restrict__ out,
                              int rows, int cols) {
    __shared__ float tile[32][33];
    int c0 = blockIdx.x * 32;
    int r0 = blockIdx.y * 32;
    int tx = threadIdx.x;   // 0..31
    int ty = threadIdx.y;   // 0..7
    #pragma unroll
    for (int i = ty; i < 32; i += 8)
        tile[i][tx] = in[(size_t)(r0 + i) * cols + (c0 + tx)];
    __syncthreads();
    #pragma unroll
    for (int i = ty; i < 32; i += 8)
        out[(size_t)(c0 + i) * rows + (r0 + tx)] = __float2half(tile[tx][i]);
}

// elementwise fp32 -> fp16 (4 elems / thread)
__global__ void convert_f2h(const float* __restrict__ in, __half* __restrict__ out, size_t n) {
    size_t i = ((size_t)blockIdx.x * blockDim.x + threadIdx.x) * 4;
    if (i + 3 < n) {
        float4 v = *reinterpret_cast<const float4*>(in + i);
        __half2 h0 = __floats2half2_rn(v.x, v.y);
        __half2 h1 = __floats2half2_rn(v.z, v.w);
        *reinterpret_cast<__half2*>(out + i)     = h0;
        *reinterpret_cast<__half2*>(out + i + 2) = h1;
    }
}

// ---------------- fp16 WMMA GEMM: C[MxN] = A[MxK] * B[KxN], all row-major ----
#define BM 128
#define BN 128
#define BK 32

__global__ __launch_bounds__(256)
void gemm_hhf(const __half* __restrict__ A, const __half* __restrict__ B,
              float* __restrict__ C, int M, int N, int K) {
    __shared__ __half As[BM][BK + 8];   // +16B pad
    __shared__ __half Bs[BK][BN + 8];

    const int tid = threadIdx.x;
    const int wid = tid >> 5;
    const int wm  = wid & 3;      // 0..3 -> 32 rows each
    const int wn  = wid >> 2;     // 0..1 -> 64 cols each

    wmma::fragment<wmma::accumulator, 16, 16, 16, float> acc[2][4];
    #pragma unroll
    for (int i = 0; i < 2; i++)
        #pragma unroll
        for (int j = 0; j < 4; j++)
            wmma::fill_fragment(acc[i][j], 0.0f);

    const size_t m0 = (size_t)blockIdx.y * BM;
    const size_t n0 = (size_t)blockIdx.x * BN;

    // global->smem load mapping
    const int arow = tid >> 2;            // 0..63 (two passes)
    const int acol = (tid & 3) * 8;       // 0,8,16,24
    const int brow = tid >> 4;            // 0..15 (two passes)
    const int bcol = (tid & 15) * 8;      // 0..120

    for (int k0 = 0; k0 < K; k0 += BK) {
        // A tile: 128 x 32
        *reinterpret_cast<uint4*>(&As[arow][acol]) =
            *reinterpret_cast<const uint4*>(&A[(m0 + arow) * (size_t)K + k0 + acol]);
        *reinterpret_cast<uint4*>(&As[arow + 64][acol]) =
            *reinterpret_cast<const uint4*>(&A[(m0 + arow + 64) * (size_t)K + k0 + acol]);
        // B tile: 32 x 128
        *reinterpret_cast<uint4*>(&Bs[brow][bcol]) =
            *reinterpret_cast<const uint4*>(&B[(size_t)(k0 + brow) * N + n0 + bcol]);
        *reinterpret_cast<uint4*>(&Bs[brow + 16][bcol]) =
            *reinterpret_cast<const uint4*>(&B[(size_t)(k0 + brow + 16) * N + n0 + bcol]);
        __syncthreads();

        #pragma unroll
        for (int kk = 0; kk < BK; kk += 16) {
            wmma::fragment<wmma::matrix_a, 16, 16, 16, __half, wmma::row_major> af[2];
            wmma::fragment<wmma::matrix_b, 16, 16, 16, __half, wmma::row_major> bf[4];
            #pragma unroll
            for (int i = 0; i < 2; i++)
                wmma::load_matrix_sync(af[i], &As[wm * 32 + i * 16][kk], BK + 8);
            #pragma unroll
            for (int j = 0; j < 4; j++)
                wmma::load_matrix_sync(bf[j], &Bs[kk][wn * 64 + j * 16], BN + 8);
            #pragma unroll
            for (int i = 0; i < 2; i++)
                #pragma unroll
                for (int j = 0; j < 4; j++)
                    wmma::mma_sync(acc[i][j], af[i], bf[j], acc[i][j]);
        }
        __syncthreads();
    }

    #pragma unroll
    for (int i = 0; i < 2; i++)
        #pragma unroll
        for (int j = 0; j < 4; j++)
            wmma::store_matrix_sync(
                &C[(m0 + wm * 32 + i * 16) * (size_t)N + n0 + wn * 64 + j * 16],
                acc[i][j], N, wmma::mem_row_major);
}

// ---------------- row softmax: logits fp32 -> unnormalized exp in fp16 -------
__global__ __launch_bounds__(256)
void softmax_rows(const float* __restrict__ S, __half* __restrict__ P,
                  float* __restrict__ rsum, int cols) {
    __shared__ float red[256];
    const int row = blockIdx.x;
    const int tid = threadIdx.x;
    const float scale = 0.015625f;   // 1/sqrt(4096)
    const float* s = S + (size_t)row * cols;
    __half* p = P + (size_t)row * cols;

    float lmax = -1e30f;
    for (int j = tid; j < cols; j += 256)
        lmax = fmaxf(lmax, s[j]);
    red[tid] = lmax;
    __syncthreads();
    #pragma unroll
    for (int st = 128; st > 0; st >>= 1) {
        if (tid < st) red[tid] = fmaxf(red[tid], red[tid + st]);
        __syncthreads();
    }
    const float m = red[0] * scale;
    __syncthreads();

    float lsum = 0.0f;
    for (int j = tid; j < cols; j += 256) {
        float e = expf(s[j] * scale - m);
        lsum += e;
        p[j] = __float2half(e);
    }
    red[tid] = lsum;
    __syncthreads();
    #pragma unroll
    for (int st = 128; st > 0; st >>= 1) {
        if (tid < st) red[tid] += red[tid + st];
        __syncthreads();
    }
    if (tid == 0) rsum[row] = red[0];
}

// ---------------- epilogue: divide each output row by its softmax sum --------
__global__ __launch_bounds__(256)
void scale_rows(float* __restrict__ C, const float* __restrict__ rsum, int cols) {
    const int row = blockIdx.y;
    const int col = (blockIdx.x * 256 + threadIdx.x) * 4;
    const float inv = 1.0f / rsum[row];
    float4* p = reinterpret_cast<float4*>(C + (size_t)row * cols + col);
    float4 v = *p;
    v.x *= inv; v.y *= inv; v.z *= inv; v.w *= inv;
    *p = v;
}

// ---------------- launch ------------------------------------------------------
extern "C" void kernel_launch(void* const* d_in, const int* in_sizes, int n_in,
                              void* d_out, int out_size) {
    const float* q = (const float*)d_in[0];   // (4096, 4096)  [n][i]
    const float* k = (const float*)d_in[1];   // (4096, 8192)  [n][j]
    const float* v = (const float*)d_in[2];   // (4096, 8192)  [v][j]
    float* out = (float*)d_out;               // (4096, 4096)  [i][v]

    __half *pQt, *pKc, *pVt, *pP;
    float *pS, *pRsum;
    cudaGetSymbolAddress((void**)&pQt,   g_Qt);
    cudaGetSymbolAddress((void**)&pKc,   g_Kc);
    cudaGetSymbolAddress((void**)&pVt,   g_Vt);
    cudaGetSymbolAddress((void**)&pS,    g_S);
    cudaGetSymbolAddress((void**)&pP,    g_P);
    cudaGetSymbolAddress((void**)&pRsum, g_rsum);

    dim3 tb(32, 8);

    // Qt[i][n] = Q[n][i] : in rows=NDIM, cols=QDIM
    transpose_f2h<<<dim3(QDIM / 32, NDIM / 32), tb>>>(q, pQt, NDIM, QDIM);
    // K convert (straight)
    {
        size_t n = (size_t)NDIM * MDIM;
        convert_f2h<<<(unsigned)(n / 4 / 256), 256>>>(k, pKc, n);
    }
    // Vt[j][v] = V[v][j] : in rows=VDIM, cols=MDIM
    transpose_f2h<<<dim3(MDIM / 32, VDIM / 32), tb>>>(v, pVt, VDIM, MDIM);

    // GEMM1: S[QDIM x MDIM] = Qt[QDIM x NDIM] * K[NDIM x MDIM]
    gemm_hhf<<<dim3(MDIM / BN, QDIM / BM), 256>>>(pQt, pKc, pS, QDIM, MDIM, NDIM);

    // softmax over rows of S -> unnormalized exp in P, sums in rsum
    softmax_rows<<<QDIM, 256>>>(pS, pP, pRsum, MDIM);

    // GEMM2: out[QDIM x VDIM] = P[QDIM x MDIM] * Vt[MDIM x VDIM]
    gemm_hhf<<<dim3(VDIM / BN, QDIM / BM), 256>>>(pP, pVt, out, QDIM, VDIM, MDIM);

    // normalize rows by softmax sum
    scale_rows<<<dim3(VDIM / 1024, QDIM), 256>>>(out, pRsum, VDIM);
}

// round 3
// speedup vs baseline: 1.4157x; 1.4157x over previous
#include <cuda_runtime.h>
#include <cuda_fp16.h>
#include <cstdint>

#define QDIM 4096   // q_dim (output rows i)
#define NDIM 4096   // contraction of GEMM1 (n)
#define MDIM 8192   // softmax dim / contraction of GEMM2 (j)
#define VDIM 4096   // v_dim (output cols v)

// ---------------- scratch (static device globals) ---------------------------
__device__ __half g_Qt[(size_t)QDIM * NDIM];   // Qt[i][n] = Q[n][i]
__device__ __half g_Kt[(size_t)MDIM * NDIM];   // Kt[j][n] = K[n][j]
__device__ __half g_Vc[(size_t)VDIM * MDIM];   // Vc[v][j] = V[v][j]
__device__ __half g_P [(size_t)QDIM * MDIM];   // exp(s) UNNORMALIZED fp16
__device__ float  g_rinv[QDIM];                // 1 / row sums

// ---------------- helpers ----------------------------------------------------
__device__ __forceinline__ uint32_t smem_u32(const void* p) {
    uint32_t a;
    asm("{ .reg .u64 t; cvta.to.shared.u64 t, %1; cvt.u32.u64 %0, t; }" : "=r"(a) : "l"(p));
    return a;
}
__device__ __forceinline__ void cp16(uint32_t dst, const void* src) {
    asm volatile("cp.async.cg.shared.global [%0], [%1], 16;" :: "r"(dst), "l"(src));
}
__device__ __forceinline__ void ldsm4(uint32_t& r0, uint32_t& r1, uint32_t& r2, uint32_t& r3,
                                      uint32_t addr) {
    asm volatile("ldmatrix.sync.aligned.m8n8.x4.shared.b16 {%0,%1,%2,%3}, [%4];"
                 : "=r"(r0), "=r"(r1), "=r"(r2), "=r"(r3) : "r"(addr));
}
__device__ __forceinline__ void mma16816(float* d, uint32_t a0, uint32_t a1, uint32_t a2,
                                         uint32_t a3, uint32_t b0, uint32_t b1) {
    asm volatile(
        "mma.sync.aligned.m16n8k16.row.col.f32.f16.f16.f32 "
        "{%0,%1,%2,%3}, {%4,%5,%6,%7}, {%8,%9}, {%0,%1,%2,%3};"
        : "+f"(d[0]), "+f"(d[1]), "+f"(d[2]), "+f"(d[3])
        : "r"(a0), "r"(a1), "r"(a2), "r"(a3), "r"(b0), "r"(b1));
}

// ---------------- preprocessing ----------------------------------------------
__global__ void transpose_f2h(const float* __restrict__ in, __half* __restrict__ out,
                              int rows, int cols) {
    __shared__ float tile[32][33];
    int c0 = blockIdx.x * 32, r0 = blockIdx.y * 32;
    int tx = threadIdx.x, ty = threadIdx.y;
    #pragma unroll
    for (int i = ty; i < 32; i += 8)
        tile[i][tx] = in[(size_t)(r0 + i) * cols + (c0 + tx)];
    __syncthreads();
    #pragma unroll
    for (int i = ty; i < 32; i += 8)
        out[(size_t)(c0 + i) * rows + (r0 + tx)] = __float2half(tile[tx][i]);
}

__global__ void convert_f2h(const float* __restrict__ in, __half* __restrict__ out, size_t n) {
    size_t i = ((size_t)blockIdx.x * blockDim.x + threadIdx.x) * 4;
    if (i + 3 < n) {
        float4 v = *reinterpret_cast<const float4*>(in + i);
        *reinterpret_cast<__half2*>(out + i)     = __floats2half2_rn(v.x, v.y);
        *reinterpret_cast<__half2*>(out + i + 2) = __floats2half2_rn(v.z, v.w);
    }
}

// ---------------- mma.sync GEMM: C[M,N] = A[M,K] @ B[N,K]^T  ------------------
// Both operands K-major fp16. 128x128 tile, BK=64, 3-stage cp.async pipeline.
// EPI=0: C = exp(scale*acc) as fp16 (unnormalized softmax numerator)
// EPI=1: C = acc * rinv[row] as fp32
#define BM 128
#define BN 128
#define BKC 64
#define STAGES 3
#define STG_BYTES (BM * 128 + BN * 128)     // 32 KB per stage (A then B)
#define SMEM_SZ (STAGES * STG_BYTES)        // 96 KB

template <int EPI>
__global__ __launch_bounds__(256, 2)
void gemm_mma(const __half* __restrict__ A, const __half* __restrict__ B,
              void* __restrict__ Cv, int M, int N, int K,
              const float* __restrict__ rinv) {
    extern __shared__ char smem[];
    const uint32_t sb = smem_u32(smem);
    const int tid = threadIdx.x;
    const int wid = tid >> 5;
    const int lane = tid & 31;
    const int wm = wid & 1;           // 2 warps over M -> 64 rows each
    const int wn = wid >> 1;          // 4 warps over N -> 32 cols each
    const size_t m0 = (size_t)blockIdx.y * BM;
    const size_t n0 = (size_t)blockIdx.x * BN;
    const int nk = K / BKC;

    // cp.async mapping: 8 chunks of 16B per 128B row
    const int ldrow = tid >> 3;          // 0..31 (xN iters)
    const int ldc16 = tid & 7;           // chunk within row
    const uint32_t swz_st = ((uint32_t)ldc16 ^ ((uint32_t)ldrow & 7)) << 4;

    auto load_stage = [&](int c, int buf) {
        const uint32_t abase = sb + buf * STG_BYTES;
        const uint32_t bbase = abase + BM * 128;
        const size_t k0 = (size_t)c * BKC;
        #pragma unroll
        for (int i = 0; i < 4; i++) {
            int row = ldrow + i * 32;
            cp16(abase + row * 128 + swz_st, A + (m0 + row) * (size_t)K + k0 + ldc16 * 8);
        }
        #pragma unroll
        for (int i = 0; i < 4; i++) {
            int row = ldrow + i * 32;
            cp16(bbase + row * 128 + swz_st, B + (n0 + row) * (size_t)K + k0 + ldc16 * 8);
        }
        asm volatile("cp.async.commit_group;" ::: "memory");
    };

    float acc[4][4][4];
    #pragma unroll
    for (int i = 0; i < 4; i++)
        #pragma unroll
        for (int j = 0; j < 4; j++)
            #pragma unroll
            for (int r = 0; r < 4; r++) acc[i][j][r] = 0.0f;

    #pragma unroll
    for (int s = 0; s < STAGES - 1; s++) load_stage(s, s);

    // ldmatrix lane addressing (swizzle XOR is lane-invariant across mi/ni16)
    const uint32_t lrow = lane & 15;               // row within 16-row group
    const uint32_t lhalf = lane >> 4;              // 0/1 -> +8 halfs in k
    const uint32_t lswz = (lane & 7);
    const uint32_t a_rowbyte = (wm * 64 + lrow) * 128;
    const uint32_t b_rowbyte = (wn * 32 + lrow) * 128;

    for (int it = 0; it < nk; it++) {
        asm volatile("cp.async.wait_group %0;" :: "n"(STAGES - 2) : "memory");
        __syncthreads();
        if (it + STAGES - 1 < nk) load_stage(it + STAGES - 1, (it + STAGES - 1) % STAGES);

        const uint32_t abase = sb + (it % STAGES) * STG_BYTES;
        const uint32_t bbase = abase + BM * 128;

        #pragma unroll
        for (int k16 = 0; k16 < 4; k16++) {
            const uint32_t c16 = (uint32_t)k16 * 2 + lhalf;
            const uint32_t coff = ((c16 ^ lswz) << 4);
            uint32_t a[4][4], b[2][4];
            #pragma unroll
            for (int mi = 0; mi < 4; mi++)
                ldsm4(a[mi][0], a[mi][1], a[mi][2], a[mi][3],
                      abase + a_rowbyte + mi * 2048 + coff);
            #pragma unroll
            for (int ni = 0; ni < 2; ni++)
                ldsm4(b[ni][0], b[ni][1], b[ni][2], b[ni][3],
                      bbase + b_rowbyte + ni * 2048 + coff);
            #pragma unroll
            for (int mi = 0; mi < 4; mi++)
                #pragma unroll
                for (int nj = 0; nj < 4; nj++)
                    mma16816(acc[mi][nj], a[mi][0], a[mi][1], a[mi][2], a[mi][3],
                             b[nj >> 1][nj & 1], b[nj >> 1][(nj & 1) + 2]);
        }
        __syncthreads();
    }

    // ---- epilogue -----------------------------------------------------------
    const float scale = 0.015625f;     // 1/sqrt(4096)
    #pragma unroll
    for (int mi = 0; mi < 4; mi++) {
        const size_t r0 = m0 + wm * 64 + mi * 16 + (lane >> 2);
        const size_t r1 = r0 + 8;
        float i0 = 0.f, i1 = 0.f;
        if (EPI == 1) { i0 = rinv[r0]; i1 = rinv[r1]; }
        #pragma unroll
        for (int nj = 0; nj < 4; nj++) {
            const size_t col = n0 + wn * 32 + nj * 8 + (lane & 3) * 2;
            float* c = acc[mi][nj];
            if (EPI == 0) {
                __half* C = (__half*)Cv;
                *reinterpret_cast<__half2*>(&C[r0 * (size_t)N + col]) =
                    __floats2half2_rn(__expf(c[0] * scale), __expf(c[1] * scale));
                *reinterpret_cast<__half2*>(&C[r1 * (size_t)N + col]) =
                    __floats2half2_rn(__expf(c[2] * scale), __expf(c[3] * scale));
            } else {
                float* C = (float*)Cv;
                *reinterpret_cast<float2*>(&C[r0 * (size_t)N + col]) =
                    make_float2(c[0] * i0, c[1] * i0);
                *reinterpret_cast<float2*>(&C[r1 * (size_t)N + col]) =
                    make_float2(c[2] * i1, c[3] * i1);
            }
        }
    }
}

// ---------------- row sums of P -> reciprocal --------------------------------
__global__ __launch_bounds__(256)
void rowsum_recip(const __half* __restrict__ P, float* __restrict__ rinv, int cols) {
    __shared__ float red[256];
    const int row = blockIdx.x;
    const int tid = threadIdx.x;
    const __half2* p = reinterpret_cast<const __half2*>(P + (size_t)row * cols);
    float s = 0.0f;
    for (int j = tid; j < cols / 2; j += 256) {
        float2 v = __half22float2(p[j]);
        s += v.x + v.y;
    }
    red[tid] = s;
    __syncthreads();
    #pragma unroll
    for (int st = 128; st > 0; st >>= 1) {
        if (tid < st) red[tid] += red[tid + st];
        __syncthreads();
    }
    if (tid == 0) rinv[row] = 1.0f / red[0];
}

// ---------------- launch ------------------------------------------------------
extern "C" void kernel_launch(void* const* d_in, const int* in_sizes, int n_in,
                              void* d_out, int out_size) {
    const float* q = (const float*)d_in[0];   // (4096, 4096)  Q[n][i]
    const float* k = (const float*)d_in[1];   // (4096, 8192)  K[n][j]
    const float* v = (const float*)d_in[2];   // (4096, 8192)  V[v][j]
    float* out = (float*)d_out;               // (4096, 4096)  out[i][v]

    __half *pQt, *pKt, *pVc, *pP;
    float* pRinv;
    cudaGetSymbolAddress((void**)&pQt,   g_Qt);
    cudaGetSymbolAddress((void**)&pKt,   g_Kt);
    cudaGetSymbolAddress((void**)&pVc,   g_Vc);
    cudaGetSymbolAddress((void**)&pP,    g_P);
    cudaGetSymbolAddress((void**)&pRinv, g_rinv);

    cudaFuncSetAttribute(gemm_mma<0>, cudaFuncAttributeMaxDynamicSharedMemorySize, SMEM_SZ);
    cudaFuncSetAttribute(gemm_mma<1>, cudaFuncAttributeMaxDynamicSharedMemorySize, SMEM_SZ);

    dim3 tb(32, 8);
    // Qt[i][n] = Q[n][i]
    transpose_f2h<<<dim3(QDIM / 32, NDIM / 32), tb>>>(q, pQt, NDIM, QDIM);
    // Kt[j][n] = K[n][j]
    transpose_f2h<<<dim3(MDIM / 32, NDIM / 32), tb>>>(k, pKt, NDIM, MDIM);
    // Vc straight convert
    {
        size_t n = (size_t)VDIM * MDIM;
        convert_f2h<<<(unsigned)(n / 4 / 256), 256>>>(v, pVc, n);
    }

    // GEMM1 + fused exp: P[i][j] = exp(scale * sum_n Qt[i][n] Kt[j][n])
    gemm_mma<0><<<dim3(MDIM / BN, QDIM / BM), 256, SMEM_SZ>>>(
        pQt, pKt, pP, QDIM, MDIM, NDIM, nullptr);

    // row sums -> reciprocals
    rowsum_recip<<<QDIM, 256>>>(pP, pRinv, MDIM);

    // GEMM2 + fused normalize: out[i][v] = rinv[i] * sum_j P[i][j] Vc[v][j]
    gemm_mma<1><<<dim3(VDIM / BN, QDIM / BM), 256, SMEM_SZ>>>(
        pP, pVc, out, QDIM, VDIM, MDIM, pRinv);
}